// round 7
// baseline (speedup 1.0000x reference)
#include <cuda_runtime.h>
#include <cuda_bf16.h>
#include <math.h>
#include <stdint.h>

#define HW 16384
#define C  768
#define EPSF 1e-8f

#define NJT   128          // j-tiles of 128 cols
#define KCHK  128          // k-chunk in int8 elements
#define NCHK  (C / KCHK)   // 6
#define ASTR  784          // A_s row stride bytes (768 + 16)
#define ASZ   (128 * ASTR)          // 100352
#define BSTR  144          // B_s row stride bytes (128 + 16)
#define BCHK  (128 * BSTR)          // 18432
#define SM_B0 ASZ
#define SM_B1 (ASZ + BCHK)
#define SM_RED (ASZ + 2 * BCHK)
#define SMEM_TOTAL (SM_RED + 512 * 8)   // 141312

// ---------------- scratch ------------------------------------------------------
__device__ __align__(16) int8_t g_bs8[(size_t)HW * C];   // B int8, TRANSPOSED [j][k]
__device__ float g_pa[6][HW];
__device__ float g_pb[6][HW];
__device__ float g_ma[6][HW];
__device__ float g_mb[6][HW];
__device__ float g_rna_cos[HW];
__device__ float g_rnb_cos[HW];
__device__ float g_inv_sa[HW];   // 127/max|a[:,i]|
__device__ float g_inv_sb[HW];   // 127/max|b[:,j]|
__device__ float g_sbn[HW];      // (max_b[j]/127) * rnb_nn[j]  (argmax weight)
__device__ int   g_bjf[HW];
__device__ float g_li[HW];

static __device__ __forceinline__ uint32_t smem_u32(const void* p) {
    uint32_t a;
    asm("{ .reg .u64 t; cvta.to.shared.u64 t, %1; cvt.u32.u64 %0, t; }" : "=r"(a) : "l"(p));
    return a;
}
static __device__ __forceinline__ int q8(float v) {
    return __float2int_rn(fminf(fmaxf(v, -127.f), 127.f));
}

// ---------------- pass 1: partial sums + maxes ---------------------------------
__global__ void scan_kernel(const float* __restrict__ A, const float* __restrict__ B) {
    int j = blockIdx.x * 256 + threadIdx.x;
    int kb = blockIdx.y;
    float sa = 0.f, sb = 0.f, ma = 0.f, mb = 0.f;
#pragma unroll 8
    for (int kk = 0; kk < 128; ++kk) {
        int k = kb * 128 + kk;
        float av = A[(size_t)k * HW + j];
        float bv = B[(size_t)k * HW + j];
        sa = fmaf(av, av, sa);
        sb = fmaf(bv, bv, sb);
        ma = fmaxf(ma, fabsf(av));
        mb = fmaxf(mb, fabsf(bv));
    }
    g_pa[kb][j] = sa; g_pb[kb][j] = sb;
    g_ma[kb][j] = ma; g_mb[kb][j] = mb;
}

__global__ void norms_fin_kernel() {
    int j = blockIdx.x * 256 + threadIdx.x;
    float sa = 0.f, sb = 0.f, ma = 0.f, mb = 0.f;
#pragma unroll
    for (int kb = 0; kb < 6; ++kb) {
        sa += g_pa[kb][j]; sb += g_pb[kb][j];
        ma = fmaxf(ma, g_ma[kb][j]); mb = fmaxf(mb, g_mb[kb][j]);
    }
    g_rna_cos[j] = 1.f / (sqrtf(sa) + EPSF);
    g_rnb_cos[j] = 1.f / (sqrtf(sb) + EPSF);
    float rnb_nn = 1.f / (sqrtf(sb + EPSF) + EPSF);
    g_inv_sa[j] = 127.f / ma;
    g_inv_sb[j] = 127.f / mb;
    g_sbn[j] = (mb / 127.f) * rnb_nn;
}

// ---------------- pass 2: quantize B + transpose to [j][k] ---------------------
__global__ void bquant_kernel(const float* __restrict__ B) {
    __shared__ int8_t tile[32][ASTR];   // 32 j rows x 768 k (+pad)
    const int tid = threadIdx.x;
    const int jb = blockIdx.x;          // 512 blocks of 32 j
    const int j = tid & 31;
    const int jg = jb * 32 + j;
    const float inv = g_inv_sb[jg];
    // read B[k][j] coalesced, quantize into SMEM [j][k]
    for (int k0 = 0; k0 < C; k0 += 8) {
        int k = k0 + (tid >> 5);
        tile[j][k] = (int8_t)q8(B[(size_t)k * HW + jg] * inv);
    }
    __syncthreads();
    // write rows [j][k] coalesced, 16B chunks
#pragma unroll
    for (int pass = 0; pass < 6; ++pass) {
        int idx = pass * 256 + tid;
        int row = idx / 48, ch = idx % 48;
        *(uint4*)(g_bs8 + (size_t)(jb * 32 + row) * C + ch * 16) =
            *(const uint4*)&tile[row][ch * 16];
    }
}

// ---------------- main kernel helpers ------------------------------------------
static __device__ __forceinline__ void prefetch_chunk(uint32_t sB, const int8_t* src, int tid) {
#pragma unroll
    for (int h = 0; h < 4; ++h) {
        int q = tid + h * 256;
        int j = q >> 3, seg = (q & 7) * 16;
        uint32_t dst = sB + j * BSTR + seg;
        const char* s = (const char*)(src + (size_t)j * C) + seg;
        asm volatile("cp.async.ca.shared.global [%0], [%1], 16;" :: "r"(dst), "l"(s));
    }
    asm volatile("cp.async.commit_group;" ::: "memory");
}

static __device__ __forceinline__ void compute_chunk(
    uint32_t sA, uint32_t sB, int warp_m, int warp_n, int L, int kbyte, int acc[4][4][4])
{
#pragma unroll
    for (int ks = 0; ks < 4; ++ks) {          // 4 x k32 steps per 128-byte chunk
        uint32_t a[4][4], b[2][4];
        const uint32_t arow = warp_m * 64 + (L & 15);
        const uint32_t acol = kbyte + ks * 32 + (L >> 4) * 16;   // bytes
#pragma unroll
        for (int mf = 0; mf < 4; ++mf) {
            uint32_t addr = sA + (arow + mf * 16) * ASTR + acol;
            asm volatile("ldmatrix.sync.aligned.m8n8.x4.shared.b16 {%0,%1,%2,%3}, [%4];"
                : "=r"(a[mf][0]), "=r"(a[mf][1]), "=r"(a[mf][2]), "=r"(a[mf][3]) : "r"(addr));
        }
#pragma unroll
        for (int np = 0; np < 2; ++np) {       // pair of n8 fragments per x4
            uint32_t jrow = warp_n * 32 + np * 16 + ((L >> 4) << 3) + (L & 7);
            uint32_t addr = sB + jrow * BSTR + ks * 32 + ((L >> 3) & 1) * 16;
            asm volatile("ldmatrix.sync.aligned.m8n8.x4.shared.b16 {%0,%1,%2,%3}, [%4];"
                : "=r"(b[np][0]), "=r"(b[np][1]), "=r"(b[np][2]), "=r"(b[np][3]) : "r"(addr));
        }
#pragma unroll
        for (int mf = 0; mf < 4; ++mf)
#pragma unroll
            for (int nf = 0; nf < 4; ++nf) {
                const uint32_t b0 = b[nf >> 1][(nf & 1) * 2];
                const uint32_t b1 = b[nf >> 1][(nf & 1) * 2 + 1];
                asm volatile("mma.sync.aligned.m16n8k32.row.col.s32.s8.s8.s32 "
                    "{%0,%1,%2,%3}, {%4,%5,%6,%7}, {%8,%9}, {%0,%1,%2,%3};"
                    : "+r"(acc[mf][nf][0]), "+r"(acc[mf][nf][1]),
                      "+r"(acc[mf][nf][2]), "+r"(acc[mf][nf][3])
                    : "r"(a[mf][0]), "r"(a[mf][1]), "r"(a[mf][2]), "r"(a[mf][3]),
                      "r"(b0), "r"(b1));
            }
    }
}

extern __shared__ __align__(16) char smem[];

__global__ __launch_bounds__(256, 1) void nnfm_main_kernel(const float* __restrict__ A) {
    const int tid = threadIdx.x;
    const int L = tid & 31;
    const int wid = tid >> 5;
    const int warp_m = wid >> 2;   // 0..1
    const int warp_n = wid & 3;    // 0..3
    const int ibase = blockIdx.x * 128;

    const uint32_t sbase = smem_u32(smem);
    const uint32_t sA = sbase;

    prefetch_chunk(sbase + SM_B0, g_bs8, tid);   // first B chunk overlaps A quant

    // Quantize A tile [k][i] -> SMEM int8 [i][k]
    {
        const int i = tid & 127;
        const int kp = (tid >> 7) * 4;   // 0 or 4
        char* dst = smem + (size_t)i * ASTR;
        const float* src = A + ibase + i;
        const float inv = g_inv_sa[ibase + i];
#pragma unroll 4
        for (int k0 = 0; k0 < C; k0 += 8) {
            int k = k0 + kp;
            int q0 = q8(src[(size_t)k * HW] * inv);
            int q1 = q8(src[(size_t)(k + 1) * HW] * inv);
            int q2 = q8(src[(size_t)(k + 2) * HW] * inv);
            int q3 = q8(src[(size_t)(k + 3) * HW] * inv);
            *(uint32_t*)(dst + k) = (uint32_t)(q0 & 0xFF) | ((uint32_t)(q1 & 0xFF) << 8)
                                  | ((uint32_t)(q2 & 0xFF) << 16) | ((uint32_t)(q3 & 0xFF) << 24);
        }
    }
    __syncthreads();

    float best[8];
    int bj[8];
#pragma unroll
    for (int s = 0; s < 8; ++s) { best[s] = -3.4e38f; bj[s] = 0; }

    for (int jt = 0; jt < NJT; ++jt) {
        int acc[4][4][4];
#pragma unroll
        for (int mf = 0; mf < 4; ++mf)
#pragma unroll
            for (int nf = 0; nf < 4; ++nf)
#pragma unroll
                for (int r = 0; r < 4; ++r) acc[mf][nf][r] = 0;

        float rnv[4][2];
#pragma unroll
        for (int nf = 0; nf < 4; ++nf)
#pragma unroll
            for (int bb = 0; bb < 2; ++bb)
                rnv[nf][bb] = g_sbn[jt * 128 + warp_n * 32 + nf * 8 + 2 * (L & 3) + bb];

        for (int c = 0; c < NCHK; ++c) {
            const int idx = jt * NCHK + c;
            if (idx + 1 < NJT * NCHK) {
                const int njt = (c == NCHK - 1) ? jt + 1 : jt;
                const int nc  = (c == NCHK - 1) ? 0 : c + 1;
                prefetch_chunk(((idx + 1) & 1) ? sbase + SM_B1 : sbase + SM_B0,
                               g_bs8 + (size_t)njt * 128 * C + nc * KCHK, tid);
                asm volatile("cp.async.wait_group 1;" ::: "memory");
            } else {
                asm volatile("cp.async.wait_group 0;" ::: "memory");
            }
            __syncthreads();
            compute_chunk(sA, (idx & 1) ? sbase + SM_B1 : sbase + SM_B0,
                          warp_m, warp_n, L, c * KCHK, acc);
            __syncthreads();
        }

#pragma unroll
        for (int mf = 0; mf < 4; ++mf)
#pragma unroll
            for (int nf = 0; nf < 4; ++nf)
#pragma unroll
                for (int r = 0; r < 4; ++r) {
                    float t = (float)acc[mf][nf][r] * rnv[nf][r & 1];
                    int slot = mf * 2 + (r >> 1);
                    if (t > best[slot]) {
                        best[slot] = t;
                        bj[slot] = jt * 128 + warp_n * 32 + nf * 8 + 2 * (L & 3) + (r & 1);
                    }
                }
    }

    // reduce across the 4 lanes sharing each row, then across warp_n via SMEM
    float* sBest = (float*)(smem + SM_RED);
    int*   sJ    = (int*)  (smem + SM_RED + 512 * 4);

#pragma unroll
    for (int slot = 0; slot < 8; ++slot) {
        float bb = best[slot];
        int jj = bj[slot];
#pragma unroll
        for (int off = 1; off < 4; off <<= 1) {
            float ob = __shfl_down_sync(0xffffffffu, bb, off, 4);
            int   oj = __shfl_down_sync(0xffffffffu, jj, off, 4);
            if (ob > bb || (ob == bb && oj < jj)) { bb = ob; jj = oj; }
        }
        if ((L & 3) == 0) {
            int mf = slot >> 1, half = slot & 1;
            int r = warp_m * 64 + mf * 16 + (L >> 2) + half * 8;
            sBest[r * 4 + warp_n] = bb;
            sJ   [r * 4 + warp_n] = jj;
        }
    }
    __syncthreads();
    if (tid < 128) {
        float bb = -3.4e38f;
        int jj = 0;
        for (int t = 0; t < 4; ++t) {
            float v = sBest[tid * 4 + t];
            int oj = sJ[tid * 4 + t];
            if (v > bb || (v == bb && oj < jj)) { bb = v; jj = oj; }
        }
        g_bjf[ibase + tid] = jj;
    }
}

// ---------------- fp32 rescore of selected pairs -------------------------------
__global__ void rescore_kernel(const float* __restrict__ A, const float* __restrict__ B) {
    const int L = threadIdx.x & 31;
    const int w = threadIdx.x >> 5;
    const int i = blockIdx.x * 8 + w;
    const int j = g_bjf[i];
    float s = 0.f;
#pragma unroll 6
    for (int k = L; k < C; k += 32)
        s = fmaf(A[(size_t)k * HW + i], B[(size_t)k * HW + j], s);
#pragma unroll
    for (int off = 16; off > 0; off >>= 1)
        s += __shfl_xor_sync(0xffffffffu, s, off);
    if (L == 0)
        g_li[i] = 1.f - s * g_rna_cos[i] * g_rnb_cos[j];
}

// ---------------- finalize -----------------------------------------------------
__global__ void finalize_kernel(float* __restrict__ out) {
    __shared__ float red[256];
    int tid = threadIdx.x;
    float s = 0.f;
    for (int i = tid; i < HW; i += 256) s += g_li[i];
    red[tid] = s;
    __syncthreads();
    for (int off = 128; off > 0; off >>= 1) {
        if (tid < off) red[tid] += red[tid + off];
        __syncthreads();
    }
    if (tid == 0) out[0] = red[0] / (float)HW;
}

// ---------------- launch --------------------------------------------------------
extern "C" void kernel_launch(void* const* d_in, const int* in_sizes, int n_in,
                              void* d_out, int out_size) {
    const float* a = (const float*)d_in[0];
    const float* b = (const float*)d_in[1];
    float* out = (float*)d_out;

    cudaFuncSetAttribute(nnfm_main_kernel, cudaFuncAttributeMaxDynamicSharedMemorySize, SMEM_TOTAL);

    scan_kernel<<<dim3(HW / 256, 6), 256>>>(a, b);
    norms_fin_kernel<<<HW / 256, 256>>>();
    bquant_kernel<<<HW / 32, 256>>>(b);
    nnfm_main_kernel<<<128, 256, SMEM_TOTAL>>>(a);
    rescore_kernel<<<HW / 8, 256>>>(a, b);
    finalize_kernel<<<1, 256>>>(out);
}

// round 8
// speedup vs baseline: 1.6157x; 1.6157x over previous
#include <cuda_runtime.h>
#include <cuda_bf16.h>
#include <math.h>
#include <stdint.h>

#define HW 16384
#define C  768
#define EPSF 1e-8f

#define NJT   128       // j-tiles of 128 cols
#define NCHK  24        // k chunks of 32
#define NCHUNKS (NJT * NCHK)
#define ASTR  1552      // A_s row stride bytes (768*2 + 16 pad -> conflict-free ldmatrix)
#define ASZ   (128 * ASTR)          // 198656
#define BSTR  80        // B slice row stride bytes (32 j * 2B + 16 pad)
#define BBUF  (32 * BSTR)           // 2560 per buffer (32 k rows)
#define SM_B  ASZ                   // 4 pairs x 2 bufs x BBUF = 20480
#define SM_RED (ASZ + 8 * BBUF)
#define SMEM_TOTAL (SM_RED + 512 * 8)   // 223232

// ---------------- scratch ------------------------------------------------------
__device__ __align__(16) __nv_bfloat16 g_bbf[(size_t)C * HW];  // B in bf16, [k][j]
__device__ float g_pa[6][HW];
__device__ float g_pb[6][HW];
__device__ float g_rna_cos[HW];
__device__ float g_rnb_cos[HW];
__device__ float g_rnb_nn[HW];
__device__ int   g_bjf[HW];
__device__ float g_li[HW];

static __device__ __forceinline__ uint32_t smem_u32(const void* p) {
    uint32_t a;
    asm("{ .reg .u64 t; cvta.to.shared.u64 t, %1; cvt.u32.u64 %0, t; }" : "=r"(a) : "l"(p));
    return a;
}

// ---------------- prep: convert B->bf16 + norm partials ------------------------
__global__ void prep_kernel(const float* __restrict__ A, const float* __restrict__ B) {
    int j = blockIdx.x * 256 + threadIdx.x;
    int kb = blockIdx.y;
    float sa = 0.f, sb = 0.f;
#pragma unroll 8
    for (int kk = 0; kk < 128; ++kk) {
        int k = kb * 128 + kk;
        float av = A[(size_t)k * HW + j];
        float bv = B[(size_t)k * HW + j];
        sa = fmaf(av, av, sa);
        sb = fmaf(bv, bv, sb);
        g_bbf[(size_t)k * HW + j] = __float2bfloat16(bv);
    }
    g_pa[kb][j] = sa;
    g_pb[kb][j] = sb;
}

__global__ void norms_fin_kernel() {
    int j = blockIdx.x * 256 + threadIdx.x;
    float sa = 0.f, sb = 0.f;
#pragma unroll
    for (int kb = 0; kb < 6; ++kb) { sa += g_pa[kb][j]; sb += g_pb[kb][j]; }
    g_rna_cos[j] = 1.f / (sqrtf(sa) + EPSF);
    g_rnb_cos[j] = 1.f / (sqrtf(sb) + EPSF);
    g_rnb_nn[j]  = 1.f / (sqrtf(sb + EPSF) + EPSF);
}

// ---------------- main kernel helpers ------------------------------------------
// Per-warp: load its half (16 k-rows) of the pair's 32k x 32j slice.
static __device__ __forceinline__ void prefetch_slice(
    uint32_t sBuf, int kbase, int jcol, int warp_m, int L)
{
#pragma unroll
    for (int h = 0; h < 2; ++h) {
        int idx = L + h * 32;           // 0..63
        int row = idx >> 2;             // 0..15
        int seg = idx & 3;              // 0..3 (16B segments of 64B row)
        int k = kbase + warp_m * 16 + row;
        const char* src = (const char*)(g_bbf + (size_t)k * HW + jcol + seg * 8);
        uint32_t dst = sBuf + (warp_m * 16 + row) * BSTR + seg * 16;
        asm volatile("cp.async.ca.shared.global [%0], [%1], 16;" :: "r"(dst), "l"(src));
    }
    asm volatile("cp.async.commit_group;" ::: "memory");
}

static __device__ __forceinline__ void compute_chunk(
    uint32_t sA, uint32_t sBuf, int warp_m, int L, int kbase, float acc[4][4][4])
{
#pragma unroll
    for (int kf = 0; kf < 2; ++kf) {
        uint32_t a[4][4], b[4][2];
        const uint32_t arow = warp_m * 64 + (L & 15);
        const uint32_t acol = kbase + kf * 16 + (L >> 4) * 8;
#pragma unroll
        for (int mf = 0; mf < 4; ++mf) {
            uint32_t addr = sA + (arow + mf * 16) * ASTR + acol * 2;
            asm volatile("ldmatrix.sync.aligned.m8n8.x4.shared.b16 {%0,%1,%2,%3}, [%4];"
                : "=r"(a[mf][0]), "=r"(a[mf][1]), "=r"(a[mf][2]), "=r"(a[mf][3]) : "r"(addr));
        }
#pragma unroll
        for (int nf = 0; nf < 4; ++nf) {
            uint32_t addr = sBuf + (kf * 16 + (L & 15)) * BSTR + nf * 16;
            asm volatile("ldmatrix.sync.aligned.m8n8.x2.trans.shared.b16 {%0,%1}, [%2];"
                : "=r"(b[nf][0]), "=r"(b[nf][1]) : "r"(addr));
        }
#pragma unroll
        for (int mf = 0; mf < 4; ++mf)
#pragma unroll
            for (int nf = 0; nf < 4; ++nf)
                asm volatile("mma.sync.aligned.m16n8k16.row.col.f32.bf16.bf16.f32 "
                    "{%0,%1,%2,%3}, {%4,%5,%6,%7}, {%8,%9}, {%0,%1,%2,%3};"
                    : "+f"(acc[mf][nf][0]), "+f"(acc[mf][nf][1]),
                      "+f"(acc[mf][nf][2]), "+f"(acc[mf][nf][3])
                    : "r"(a[mf][0]), "r"(a[mf][1]), "r"(a[mf][2]), "r"(a[mf][3]),
                      "r"(b[nf][0]), "r"(b[nf][1]));
    }
}

extern __shared__ __align__(16) char smem[];

__global__ __launch_bounds__(256, 1) void nnfm_main_kernel(const float* __restrict__ A) {
    const int tid = threadIdx.x;
    const int L = tid & 31;
    const int wid = tid >> 5;
    const int warp_m = wid >> 2;   // 0..1  (64 rows each)
    const int warp_n = wid & 3;    // 0..3  (32 cols each)
    const int ibase = blockIdx.x * 128;
    const int barid = 1 + warp_n;  // named barrier per pair (64 threads)

    const uint32_t sbase = smem_u32(smem);
    const uint32_t sA = sbase;
    const uint32_t sBpair = sbase + SM_B + warp_n * (2 * BBUF);

    // prologue: prefetch chunk 0 for this pair (overlaps A load)
    prefetch_slice(sBpair, 0, warp_n * 32, warp_m, L);

    // Load A tile [k][i] -> SMEM [i][k] as bf16, padded rows. One-time.
    {
        const int i = tid & 127;
        const int kp = tid >> 7;   // 0/1
        char* dst = smem + (size_t)i * ASTR;
        const float* src = A + ibase + i;
#pragma unroll 4
        for (int k0 = 0; k0 < C; k0 += 4) {
            int k = k0 + kp * 2;
            float x0 = src[(size_t)k * HW];
            float x1 = src[(size_t)(k + 1) * HW];
            __nv_bfloat162 h = __floats2bfloat162_rn(x0, x1);
            *(uint32_t*)(dst + k * 2) = *reinterpret_cast<uint32_t*>(&h);
        }
    }
    __syncthreads();
    asm volatile("cp.async.wait_group 0;" ::: "memory");
    asm volatile("bar.sync %0, 64;" :: "r"(barid) : "memory");

    float best[8];
    int bj[8];
#pragma unroll
    for (int s = 0; s < 8; ++s) { best[s] = -3.4e38f; bj[s] = 0; }

    for (int jt = 0; jt < NJT; ++jt) {
        float acc[4][4][4];
#pragma unroll
        for (int mf = 0; mf < 4; ++mf)
#pragma unroll
            for (int nf = 0; nf < 4; ++nf)
#pragma unroll
                for (int r = 0; r < 4; ++r) acc[mf][nf][r] = 0.f;

        float rnv[4][2];
#pragma unroll
        for (int nf = 0; nf < 4; ++nf)
#pragma unroll
            for (int bb = 0; bb < 2; ++bb)
                rnv[nf][bb] = g_rnb_nn[jt * 128 + warp_n * 32 + nf * 8 + 2 * (L & 3) + bb];

        for (int c = 0; c < NCHK; ++c) {
            const int t = jt * NCHK + c;
            const int have_next = (t + 1 < NCHUNKS);
            if (have_next) {
                const int njt = (c == NCHK - 1) ? jt + 1 : jt;
                const int nc  = (c == NCHK - 1) ? 0 : c + 1;
                prefetch_slice(sBpair + ((t + 1) & 1) * BBUF,
                               nc * 32, njt * 128 + warp_n * 32, warp_m, L);
            }
            compute_chunk(sA, sBpair + (t & 1) * BBUF, warp_m, L, c * 32, acc);
            if (have_next)
                asm volatile("cp.async.wait_group 0;" ::: "memory");
            asm volatile("bar.sync %0, 64;" :: "r"(barid) : "memory");
        }

        // fold tile into running argmax (j ascending; strict > keeps lowest j)
#pragma unroll
        for (int mf = 0; mf < 4; ++mf)
#pragma unroll
            for (int nf = 0; nf < 4; ++nf)
#pragma unroll
                for (int r = 0; r < 4; ++r) {
                    float t = acc[mf][nf][r] * rnv[nf][r & 1];
                    int slot = mf * 2 + (r >> 1);
                    if (t > best[slot]) {
                        best[slot] = t;
                        bj[slot] = jt * 128 + warp_n * 32 + nf * 8 + 2 * (L & 3) + (r & 1);
                    }
                }
    }

    // reduce across the 4 lanes sharing each row, then across warp_n via SMEM
    float* sBest = (float*)(smem + SM_RED);
    int*   sJ    = (int*)  (smem + SM_RED + 512 * 4);

#pragma unroll
    for (int slot = 0; slot < 8; ++slot) {
        float bb = best[slot];
        int jj = bj[slot];
#pragma unroll
        for (int off = 1; off < 4; off <<= 1) {
            float ob = __shfl_down_sync(0xffffffffu, bb, off, 4);
            int   oj = __shfl_down_sync(0xffffffffu, jj, off, 4);
            if (ob > bb || (ob == bb && oj < jj)) { bb = ob; jj = oj; }
        }
        if ((L & 3) == 0) {
            int mf = slot >> 1, half = slot & 1;
            int r = warp_m * 64 + mf * 16 + (L >> 2) + half * 8;
            sBest[r * 4 + warp_n] = bb;
            sJ   [r * 4 + warp_n] = jj;
        }
    }
    __syncthreads();
    if (tid < 128) {
        float bb = -3.4e38f;
        int jj = 0;
        for (int t = 0; t < 4; ++t) {
            float v = sBest[tid * 4 + t];
            int oj = sJ[tid * 4 + t];
            if (v > bb || (v == bb && oj < jj)) { bb = v; jj = oj; }
        }
        g_bjf[ibase + tid] = jj;
    }
}

// ---------------- fp32 rescore of selected pairs (kills winner's-curse bias) ---
__global__ void rescore_kernel(const float* __restrict__ A, const float* __restrict__ B) {
    const int L = threadIdx.x & 31;
    const int w = threadIdx.x >> 5;
    const int i = blockIdx.x * 8 + w;
    const int j = g_bjf[i];
    float s = 0.f;
#pragma unroll 6
    for (int k = L; k < C; k += 32)
        s = fmaf(A[(size_t)k * HW + i], B[(size_t)k * HW + j], s);
#pragma unroll
    for (int off = 16; off > 0; off >>= 1)
        s += __shfl_xor_sync(0xffffffffu, s, off);
    if (L == 0)
        g_li[i] = 1.f - s * g_rna_cos[i] * g_rnb_cos[j];
}

// ---------------- finalize -----------------------------------------------------
__global__ void finalize_kernel(float* __restrict__ out) {
    __shared__ float red[256];
    int tid = threadIdx.x;
    float s = 0.f;
    for (int i = tid; i < HW; i += 256) s += g_li[i];
    red[tid] = s;
    __syncthreads();
    for (int off = 128; off > 0; off >>= 1) {
        if (tid < off) red[tid] += red[tid + off];
        __syncthreads();
    }
    if (tid == 0) out[0] = red[0] / (float)HW;
}

// ---------------- launch --------------------------------------------------------
extern "C" void kernel_launch(void* const* d_in, const int* in_sizes, int n_in,
                              void* d_out, int out_size) {
    const float* a = (const float*)d_in[0];
    const float* b = (const float*)d_in[1];
    float* out = (float*)d_out;

    cudaFuncSetAttribute(nnfm_main_kernel, cudaFuncAttributeMaxDynamicSharedMemorySize, SMEM_TOTAL);

    prep_kernel<<<dim3(HW / 256, 6), 256>>>(a, b);
    norms_fin_kernel<<<HW / 256, 256>>>();
    nnfm_main_kernel<<<128, 256, SMEM_TOTAL>>>(a);
    rescore_kernel<<<HW / 8, 256>>>(a, b);
    finalize_kernel<<<1, 256>>>(out);
}

// round 9
// speedup vs baseline: 1.8281x; 1.1315x over previous
#include <cuda_runtime.h>
#include <cuda_bf16.h>
#include <math.h>
#include <stdint.h>

#define HW 16384
#define C  768
#define EPSF 1e-8f

#define NJT   128       // j-tiles of 128 cols
#define NCHK  24        // k chunks of 32
#define NCHUNKS (NJT * NCHK)
#define NSTG  3         // pipeline stages
#define ASTR  1552      // A_s row stride bytes (768*2 + 16 pad -> conflict-free ldmatrix)
#define ASZ   (128 * ASTR)          // 198656
#define BSTR  272       // B_s row stride bytes (128*2 + 16 pad)
#define BCHK  (32 * BSTR)           // 8704 per buffer
#define SM_RED (ASZ + NSTG * BCHK)  // reduction area
#define SMEM_TOTAL (SM_RED + 512 * 8)   // 228864

// ---------------- scratch ------------------------------------------------------
__device__ __align__(16) __nv_bfloat16 g_bbf[(size_t)C * HW];  // B in bf16, [k][j]
__device__ float g_pa[6][HW];
__device__ float g_pb[6][HW];
__device__ float g_rna_cos[HW];
__device__ float g_rnb_cos[HW];
__device__ float g_rnb_nn[HW];
__device__ int   g_bjf[HW];
__device__ float g_li[HW];

static __device__ __forceinline__ uint32_t smem_u32(const void* p) {
    uint32_t a;
    asm("{ .reg .u64 t; cvta.to.shared.u64 t, %1; cvt.u32.u64 %0, t; }" : "=r"(a) : "l"(p));
    return a;
}

// ---------------- prep: convert B->bf16 + norm partials ------------------------
__global__ void prep_kernel(const float* __restrict__ A, const float* __restrict__ B) {
    int j = blockIdx.x * 256 + threadIdx.x;
    int kb = blockIdx.y;
    float sa = 0.f, sb = 0.f;
#pragma unroll 8
    for (int kk = 0; kk < 128; ++kk) {
        int k = kb * 128 + kk;
        float av = A[(size_t)k * HW + j];
        float bv = B[(size_t)k * HW + j];
        sa = fmaf(av, av, sa);
        sb = fmaf(bv, bv, sb);
        g_bbf[(size_t)k * HW + j] = __float2bfloat16(bv);
    }
    g_pa[kb][j] = sa;
    g_pb[kb][j] = sb;
}

__global__ void norms_fin_kernel() {
    int j = blockIdx.x * 256 + threadIdx.x;
    float sa = 0.f, sb = 0.f;
#pragma unroll
    for (int kb = 0; kb < 6; ++kb) { sa += g_pa[kb][j]; sb += g_pb[kb][j]; }
    g_rna_cos[j] = 1.f / (sqrtf(sa) + EPSF);
    g_rnb_cos[j] = 1.f / (sqrtf(sb) + EPSF);
    g_rnb_nn[j]  = 1.f / (sqrtf(sb + EPSF) + EPSF);
}

// ---------------- main kernel helpers ------------------------------------------
static __device__ __forceinline__ void prefetch_chunk(uint32_t sB, const __nv_bfloat16* src, int tid) {
#pragma unroll
    for (int h = 0; h < 2; ++h) {
        int q = tid + h * 256;
        int k = q >> 4, seg = q & 15;
        uint32_t dst = sB + k * BSTR + seg * 16;
        const char* s = (const char*)(src + (size_t)k * HW) + seg * 16;
        asm volatile("cp.async.ca.shared.global [%0], [%1], 16;" :: "r"(dst), "l"(s));
    }
    asm volatile("cp.async.commit_group;" ::: "memory");
}

static __device__ __forceinline__ void compute_chunk(
    uint32_t sA, uint32_t sB, int warp_m, int warp_n, int L, int kbase, float acc[4][4][4])
{
#pragma unroll
    for (int kf = 0; kf < 2; ++kf) {
        uint32_t a[4][4], b[4][2];
        const uint32_t arow = warp_m * 64 + (L & 15);
        const uint32_t acol = kbase + kf * 16 + (L >> 4) * 8;
#pragma unroll
        for (int mf = 0; mf < 4; ++mf) {
            uint32_t addr = sA + (arow + mf * 16) * ASTR + acol * 2;
            asm volatile("ldmatrix.sync.aligned.m8n8.x4.shared.b16 {%0,%1,%2,%3}, [%4];"
                : "=r"(a[mf][0]), "=r"(a[mf][1]), "=r"(a[mf][2]), "=r"(a[mf][3]) : "r"(addr));
        }
#pragma unroll
        for (int nf = 0; nf < 4; ++nf) {
            uint32_t addr = sB + (kf * 16 + (L & 15)) * BSTR + (warp_n * 32 + nf * 8) * 2;
            asm volatile("ldmatrix.sync.aligned.m8n8.x2.trans.shared.b16 {%0,%1}, [%2];"
                : "=r"(b[nf][0]), "=r"(b[nf][1]) : "r"(addr));
        }
#pragma unroll
        for (int mf = 0; mf < 4; ++mf)
#pragma unroll
            for (int nf = 0; nf < 4; ++nf)
                asm volatile("mma.sync.aligned.m16n8k16.row.col.f32.bf16.bf16.f32 "
                    "{%0,%1,%2,%3}, {%4,%5,%6,%7}, {%8,%9}, {%0,%1,%2,%3};"
                    : "+f"(acc[mf][nf][0]), "+f"(acc[mf][nf][1]),
                      "+f"(acc[mf][nf][2]), "+f"(acc[mf][nf][3])
                    : "r"(a[mf][0]), "r"(a[mf][1]), "r"(a[mf][2]), "r"(a[mf][3]),
                      "r"(b[nf][0]), "r"(b[nf][1]));
    }
}

extern __shared__ __align__(16) char smem[];

__global__ __launch_bounds__(256, 1) void nnfm_main_kernel(const float* __restrict__ A) {
    const int tid = threadIdx.x;
    const int L = tid & 31;
    const int wid = tid >> 5;
    const int warp_m = wid >> 2;   // 0..1  (64 rows each)
    const int warp_n = wid & 3;    // 0..3  (32 cols each)
    const int ibase = blockIdx.x * 128;

    const uint32_t sbase = smem_u32(smem);
    const uint32_t sA = sbase;
    const uint32_t sB0 = sbase + ASZ;

    // prologue: prefetch chunks 0 and 1 (overlaps the A load below)
    prefetch_chunk(sB0,        g_bbf, tid);                       // chunk 0 -> buf 0
    prefetch_chunk(sB0 + BCHK, g_bbf + (size_t)32 * HW, tid);     // chunk 1 -> buf 1

    // Load A tile [k][i] -> SMEM [i][k] as bf16, padded rows. One-time.
    {
        const int i = tid & 127;
        const int kp = tid >> 7;   // 0/1
        char* dst = smem + (size_t)i * ASTR;
        const float* src = A + ibase + i;
#pragma unroll 4
        for (int k0 = 0; k0 < C; k0 += 4) {
            int k = k0 + kp * 2;
            float x0 = src[(size_t)k * HW];
            float x1 = src[(size_t)(k + 1) * HW];
            __nv_bfloat162 h = __floats2bfloat162_rn(x0, x1);
            *(uint32_t*)(dst + k * 2) = *reinterpret_cast<uint32_t*>(&h);
        }
    }

    float best[8];
    int bj[8];
#pragma unroll
    for (int s = 0; s < 8; ++s) { best[s] = -3.4e38f; bj[s] = 0; }

    int t = 0;       // global chunk index
    int stg2 = 2;    // (t+2) % NSTG, maintained incrementally
    for (int jt = 0; jt < NJT; ++jt) {
        float acc[4][4][4];
#pragma unroll
        for (int mf = 0; mf < 4; ++mf)
#pragma unroll
            for (int nf = 0; nf < 4; ++nf)
#pragma unroll
                for (int r = 0; r < 4; ++r) acc[mf][nf][r] = 0.f;

        float rnv[4][2];
#pragma unroll
        for (int nf = 0; nf < 4; ++nf)
#pragma unroll
            for (int bb = 0; bb < 2; ++bb)
                rnv[nf][bb] = g_rnb_nn[jt * 128 + warp_n * 32 + nf * 8 + 2 * (L & 3) + bb];

        for (int c = 0; c < NCHK; ++c) {
            // chunk t must be resident: allow only the newest (t+1) in flight
            asm volatile("cp.async.wait_group 1;" ::: "memory");
            __syncthreads();
            // prefetch chunk t+2 into the stage freed by chunk t-1
            if (t + 2 < NCHUNKS) {
                const int t2 = t + 2;
                const int njt = t2 / NCHK, nc = t2 - njt * NCHK;
                prefetch_chunk(sB0 + stg2 * BCHK,
                               g_bbf + (size_t)(nc * 32) * HW + (size_t)njt * 128, tid);
            }
            compute_chunk(sA, sB0 + (t % NSTG) * BCHK, warp_m, warp_n, L, c * 32, acc);
            ++t;
            stg2 = (stg2 == NSTG - 1) ? 0 : stg2 + 1;
        }

        // fold tile into running argmax (j ascending; strict > keeps lowest j)
#pragma unroll
        for (int mf = 0; mf < 4; ++mf)
#pragma unroll
            for (int nf = 0; nf < 4; ++nf)
#pragma unroll
                for (int r = 0; r < 4; ++r) {
                    float v = acc[mf][nf][r] * rnv[nf][r & 1];
                    int slot = mf * 2 + (r >> 1);
                    if (v > best[slot]) {
                        best[slot] = v;
                        bj[slot] = jt * 128 + warp_n * 32 + nf * 8 + 2 * (L & 3) + (r & 1);
                    }
                }
    }

    // reduce across the 4 lanes sharing each row, then across warp_n via SMEM
    float* sBest = (float*)(smem + SM_RED);
    int*   sJ    = (int*)  (smem + SM_RED + 512 * 4);

#pragma unroll
    for (int slot = 0; slot < 8; ++slot) {
        float bb = best[slot];
        int jj = bj[slot];
#pragma unroll
        for (int off = 1; off < 4; off <<= 1) {
            float ob = __shfl_down_sync(0xffffffffu, bb, off, 4);
            int   oj = __shfl_down_sync(0xffffffffu, jj, off, 4);
            if (ob > bb || (ob == bb && oj < jj)) { bb = ob; jj = oj; }
        }
        if ((L & 3) == 0) {
            int mf = slot >> 1, half = slot & 1;
            int r = warp_m * 64 + mf * 16 + (L >> 2) + half * 8;
            sBest[r * 4 + warp_n] = bb;
            sJ   [r * 4 + warp_n] = jj;
        }
    }
    __syncthreads();
    if (tid < 128) {
        float bb = -3.4e38f;
        int jj = 0;
        for (int u = 0; u < 4; ++u) {
            float v = sBest[tid * 4 + u];
            int oj = sJ[tid * 4 + u];
            if (v > bb || (v == bb && oj < jj)) { bb = v; jj = oj; }
        }
        g_bjf[ibase + tid] = jj;
    }
}

// ---------------- fp32 rescore of selected pairs (kills winner's-curse bias) ---
__global__ void rescore_kernel(const float* __restrict__ A, const float* __restrict__ B) {
    const int L = threadIdx.x & 31;
    const int w = threadIdx.x >> 5;
    const int i = blockIdx.x * 8 + w;
    const int j = g_bjf[i];
    float s = 0.f;
#pragma unroll 6
    for (int k = L; k < C; k += 32)
        s = fmaf(A[(size_t)k * HW + i], B[(size_t)k * HW + j], s);
#pragma unroll
    for (int off = 16; off > 0; off >>= 1)
        s += __shfl_xor_sync(0xffffffffu, s, off);
    if (L == 0)
        g_li[i] = 1.f - s * g_rna_cos[i] * g_rnb_cos[j];
}

// ---------------- finalize -----------------------------------------------------
__global__ void finalize_kernel(float* __restrict__ out) {
    __shared__ float red[256];
    int tid = threadIdx.x;
    float s = 0.f;
    for (int i = tid; i < HW; i += 256) s += g_li[i];
    red[tid] = s;
    __syncthreads();
    for (int off = 128; off > 0; off >>= 1) {
        if (tid < off) red[tid] += red[tid + off];
        __syncthreads();
    }
    if (tid == 0) out[0] = red[0] / (float)HW;
}

// ---------------- launch --------------------------------------------------------
extern "C" void kernel_launch(void* const* d_in, const int* in_sizes, int n_in,
                              void* d_out, int out_size) {
    const float* a = (const float*)d_in[0];
    const float* b = (const float*)d_in[1];
    float* out = (float*)d_out;

    cudaFuncSetAttribute(nnfm_main_kernel, cudaFuncAttributeMaxDynamicSharedMemorySize, SMEM_TOTAL);

    prep_kernel<<<dim3(HW / 256, 6), 256>>>(a, b);
    norms_fin_kernel<<<HW / 256, 256>>>();
    nnfm_main_kernel<<<128, 256, SMEM_TOTAL>>>(a);
    rescore_kernel<<<HW / 8, 256>>>(a, b);
    finalize_kernel<<<1, 256>>>(out);
}

// round 10
// speedup vs baseline: 1.9811x; 1.0837x over previous
#include <cuda_runtime.h>
#include <cuda_bf16.h>
#include <math.h>
#include <stdint.h>

#define HW 16384
#define C  768
#define EPSF 1e-8f

#define NJT   128       // j-tiles of 128 cols
#define KR    48        // k rows per chunk
#define NCHK  16        // chunks per tile (768/48)
#define ASTR  1552      // A_s row stride bytes (768*2 + 16 pad -> conflict-free ldmatrix)
#define ASZ   (128 * ASTR)          // 198656
#define BSTR  272       // B_s row stride bytes (128*2 + 16 pad)
#define BCHK  (KR * BSTR)           // 13056 per buffer
#define SM_B0 ASZ
#define SM_B1 (ASZ + BCHK)
#define SM_RED (ASZ + 2 * BCHK)     // reduction area: 512 best + 512 j
#define SMEM_TOTAL (SM_RED + 512 * 8)   // 228864

// ---------------- scratch ------------------------------------------------------
__device__ __align__(16) __nv_bfloat16 g_bbf[(size_t)C * HW];  // B in bf16, [k][j]
__device__ float g_pa[6][HW];
__device__ float g_pb[6][HW];
__device__ float g_rna_cos[HW];
__device__ float g_rnb_cos[HW];
__device__ float g_rnb_nn[HW];
__device__ int   g_bjf[HW];
__device__ float g_li[HW];

static __device__ __forceinline__ uint32_t smem_u32(const void* p) {
    uint32_t a;
    asm("{ .reg .u64 t; cvta.to.shared.u64 t, %1; cvt.u32.u64 %0, t; }" : "=r"(a) : "l"(p));
    return a;
}

// ---------------- prep: convert B->bf16 + norm partials ------------------------
__global__ void prep_kernel(const float* __restrict__ A, const float* __restrict__ B) {
    int j = blockIdx.x * 256 + threadIdx.x;
    int kb = blockIdx.y;
    float sa = 0.f, sb = 0.f;
#pragma unroll 8
    for (int kk = 0; kk < 128; ++kk) {
        int k = kb * 128 + kk;
        float av = A[(size_t)k * HW + j];
        float bv = B[(size_t)k * HW + j];
        sa = fmaf(av, av, sa);
        sb = fmaf(bv, bv, sb);
        g_bbf[(size_t)k * HW + j] = __float2bfloat16(bv);
    }
    g_pa[kb][j] = sa;
    g_pb[kb][j] = sb;
}

__global__ void norms_fin_kernel() {
    int j = blockIdx.x * 256 + threadIdx.x;
    float sa = 0.f, sb = 0.f;
#pragma unroll
    for (int kb = 0; kb < 6; ++kb) { sa += g_pa[kb][j]; sb += g_pb[kb][j]; }
    g_rna_cos[j] = 1.f / (sqrtf(sa) + EPSF);
    g_rnb_cos[j] = 1.f / (sqrtf(sb) + EPSF);
    g_rnb_nn[j]  = 1.f / (sqrtf(sb + EPSF) + EPSF);
}

// ---------------- main kernel helpers ------------------------------------------
static __device__ __forceinline__ void prefetch_chunk(uint32_t sB, const __nv_bfloat16* src, int tid) {
#pragma unroll
    for (int h = 0; h < 3; ++h) {           // 48 rows x 256B = 768 x 16B segs
        int q = tid + h * 256;
        int k = q >> 4, seg = q & 15;
        uint32_t dst = sB + k * BSTR + seg * 16;
        const char* s = (const char*)(src + (size_t)k * HW) + seg * 16;
        asm volatile("cp.async.ca.shared.global [%0], [%1], 16;" :: "r"(dst), "l"(s));
    }
    asm volatile("cp.async.commit_group;" ::: "memory");
}

static __device__ __forceinline__ void compute_chunk(
    uint32_t sA, uint32_t sB, int warp_m, int warp_n, int L, int kbase, float acc[4][4][4])
{
#pragma unroll
    for (int kf = 0; kf < 3; ++kf) {        // 3 x k16 steps per 48-row chunk
        uint32_t a[4][4], b[4][2];
        const uint32_t arow = warp_m * 64 + (L & 15);
        const uint32_t acol = kbase + kf * 16 + (L >> 4) * 8;
#pragma unroll
        for (int mf = 0; mf < 4; ++mf) {
            uint32_t addr = sA + (arow + mf * 16) * ASTR + acol * 2;
            asm volatile("ldmatrix.sync.aligned.m8n8.x4.shared.b16 {%0,%1,%2,%3}, [%4];"
                : "=r"(a[mf][0]), "=r"(a[mf][1]), "=r"(a[mf][2]), "=r"(a[mf][3]) : "r"(addr));
        }
#pragma unroll
        for (int nf = 0; nf < 4; ++nf) {
            uint32_t addr = sB + (kf * 16 + (L & 15)) * BSTR + (warp_n * 32 + nf * 8) * 2;
            asm volatile("ldmatrix.sync.aligned.m8n8.x2.trans.shared.b16 {%0,%1}, [%2];"
                : "=r"(b[nf][0]), "=r"(b[nf][1]) : "r"(addr));
        }
#pragma unroll
        for (int mf = 0; mf < 4; ++mf)
#pragma unroll
            for (int nf = 0; nf < 4; ++nf)
                asm volatile("mma.sync.aligned.m16n8k16.row.col.f32.bf16.bf16.f32 "
                    "{%0,%1,%2,%3}, {%4,%5,%6,%7}, {%8,%9}, {%0,%1,%2,%3};"
                    : "+f"(acc[mf][nf][0]), "+f"(acc[mf][nf][1]),
                      "+f"(acc[mf][nf][2]), "+f"(acc[mf][nf][3])
                    : "r"(a[mf][0]), "r"(a[mf][1]), "r"(a[mf][2]), "r"(a[mf][3]),
                      "r"(b[nf][0]), "r"(b[nf][1]));
    }
}

extern __shared__ __align__(16) char smem[];

__global__ __launch_bounds__(256, 1) void nnfm_main_kernel(const float* __restrict__ A) {
    const int tid = threadIdx.x;
    const int L = tid & 31;
    const int wid = tid >> 5;
    const int warp_m = wid >> 2;   // 0..1  (64 rows each)
    const int warp_n = wid & 3;    // 0..3  (32 cols each)
    const int ibase = blockIdx.x * 128;

    const uint32_t sbase = smem_u32(smem);
    const uint32_t sA = sbase;

    // kick off first B chunk copy immediately (overlaps A load)
    prefetch_chunk(sbase + SM_B0, g_bbf, tid);

    // Load A tile [k][i] -> SMEM [i][k] as bf16, padded rows. One-time.
    {
        const int i = tid & 127;
        const int kp = tid >> 7;   // 0/1
        char* dst = smem + (size_t)i * ASTR;
        const float* src = A + ibase + i;
#pragma unroll 4
        for (int k0 = 0; k0 < C; k0 += 4) {
            int k = k0 + kp * 2;
            float x0 = src[(size_t)k * HW];
            float x1 = src[(size_t)(k + 1) * HW];
            __nv_bfloat162 h = __floats2bfloat162_rn(x0, x1);
            *(uint32_t*)(dst + k * 2) = *reinterpret_cast<uint32_t*>(&h);
        }
    }
    __syncthreads();

    float best[8];
    int bj[8];
#pragma unroll
    for (int s = 0; s < 8; ++s) { best[s] = -3.4e38f; bj[s] = 0; }

    for (int jt = 0; jt < NJT; ++jt) {
        float acc[4][4][4];
#pragma unroll
        for (int mf = 0; mf < 4; ++mf)
#pragma unroll
            for (int nf = 0; nf < 4; ++nf)
#pragma unroll
                for (int r = 0; r < 4; ++r) acc[mf][nf][r] = 0.f;

        float rnv[4][2];
#pragma unroll
        for (int nf = 0; nf < 4; ++nf)
#pragma unroll
            for (int bb = 0; bb < 2; ++bb)
                rnv[nf][bb] = g_rnb_nn[jt * 128 + warp_n * 32 + nf * 8 + 2 * (L & 3) + bb];

        for (int c = 0; c < NCHK; ++c) {
            const int idx = jt * NCHK + c;
            if (idx + 1 < NJT * NCHK) {
                const int njt = (c == NCHK - 1) ? jt + 1 : jt;
                const int nc  = (c == NCHK - 1) ? 0 : c + 1;
                prefetch_chunk(((idx + 1) & 1) ? sbase + SM_B1 : sbase + SM_B0,
                               g_bbf + (size_t)(nc * KR) * HW + (size_t)njt * 128, tid);
                asm volatile("cp.async.wait_group 1;" ::: "memory");
            } else {
                asm volatile("cp.async.wait_group 0;" ::: "memory");
            }
            __syncthreads();
            compute_chunk(sA, (idx & 1) ? sbase + SM_B1 : sbase + SM_B0,
                          warp_m, warp_n, L, c * KR, acc);
            __syncthreads();
        }

        // fold tile into running argmax (j ascending; strict > keeps lowest j)
#pragma unroll
        for (int mf = 0; mf < 4; ++mf)
#pragma unroll
            for (int nf = 0; nf < 4; ++nf)
#pragma unroll
                for (int r = 0; r < 4; ++r) {
                    float t = acc[mf][nf][r] * rnv[nf][r & 1];
                    int slot = mf * 2 + (r >> 1);
                    if (t > best[slot]) {
                        best[slot] = t;
                        bj[slot] = jt * 128 + warp_n * 32 + nf * 8 + 2 * (L & 3) + (r & 1);
                    }
                }
    }

    // reduce across the 4 lanes sharing each row, then across warp_n via SMEM
    float* sBest = (float*)(smem + SM_RED);
    int*   sJ    = (int*)  (smem + SM_RED + 512 * 4);

#pragma unroll
    for (int slot = 0; slot < 8; ++slot) {
        float bb = best[slot];
        int jj = bj[slot];
#pragma unroll
        for (int off = 1; off < 4; off <<= 1) {
            float ob = __shfl_down_sync(0xffffffffu, bb, off, 4);
            int   oj = __shfl_down_sync(0xffffffffu, jj, off, 4);
            if (ob > bb || (ob == bb && oj < jj)) { bb = ob; jj = oj; }
        }
        if ((L & 3) == 0) {
            int mf = slot >> 1, half = slot & 1;
            int r = warp_m * 64 + mf * 16 + (L >> 2) + half * 8;
            sBest[r * 4 + warp_n] = bb;
            sJ   [r * 4 + warp_n] = jj;
        }
    }
    __syncthreads();
    if (tid < 128) {
        float bb = -3.4e38f;
        int jj = 0;
        for (int u = 0; u < 4; ++u) {
            float v = sBest[tid * 4 + u];
            int oj = sJ[tid * 4 + u];
            if (v > bb || (v == bb && oj < jj)) { bb = v; jj = oj; }
        }
        g_bjf[ibase + tid] = jj;
    }
}

// ---------------- fp32 rescore of selected pairs (kills winner's-curse bias) ---
__global__ void rescore_kernel(const float* __restrict__ A, const float* __restrict__ B) {
    const int L = threadIdx.x & 31;
    const int w = threadIdx.x >> 5;
    const int i = blockIdx.x * 8 + w;
    const int j = g_bjf[i];
    float s = 0.f;
#pragma unroll 6
    for (int k = L; k < C; k += 32)
        s = fmaf(A[(size_t)k * HW + i], B[(size_t)k * HW + j], s);
#pragma unroll
    for (int off = 16; off > 0; off >>= 1)
        s += __shfl_xor_sync(0xffffffffu, s, off);
    if (L == 0)
        g_li[i] = 1.f - s * g_rna_cos[i] * g_rnb_cos[j];
}

// ---------------- finalize -----------------------------------------------------
__global__ void finalize_kernel(float* __restrict__ out) {
    __shared__ float red[256];
    int tid = threadIdx.x;
    float s = 0.f;
    for (int i = tid; i < HW; i += 256) s += g_li[i];
    red[tid] = s;
    __syncthreads();
    for (int off = 128; off > 0; off >>= 1) {
        if (tid < off) red[tid] += red[tid + off];
        __syncthreads();
    }
    if (tid == 0) out[0] = red[0] / (float)HW;
}

// ---------------- launch --------------------------------------------------------
extern "C" void kernel_launch(void* const* d_in, const int* in_sizes, int n_in,
                              void* d_out, int out_size) {
    const float* a = (const float*)d_in[0];
    const float* b = (const float*)d_in[1];
    float* out = (float*)d_out;

    cudaFuncSetAttribute(nnfm_main_kernel, cudaFuncAttributeMaxDynamicSharedMemorySize, SMEM_TOTAL);

    prep_kernel<<<dim3(HW / 256, 6), 256>>>(a, b);
    norms_fin_kernel<<<HW / 256, 256>>>();
    nnfm_main_kernel<<<128, 256, SMEM_TOTAL>>>(a);
    rescore_kernel<<<HW / 8, 256>>>(a, b);
    finalize_kernel<<<1, 256>>>(out);
}